// round 2
// baseline (speedup 1.0000x reference)
#include <cuda_runtime.h>
#include <cuda_bf16.h>

// Problem constants
#define BB 8
#define SS 4096
#define DD 1024
#define AA 3
#define CC 2
#define NC 6            // A*C
#define KK 64           // sample_num
#define MARGIN 5.0f

#define ROWS_TOTAL (BB * SS)      // 32768
#define FLAT_PER_B (SS * AA)      // 12288

// Output packing (float32 concat in reference return order)
#define OFF_LOSS 0
#define OFF_PL   1                         // predict_label (B,S,A) = 98304
#define OFF_TI   (1 + ROWS_TOTAL * AA)     // total_idx (B*K,3) = 1536
#define OFF_CL   (OFF_TI + BB * KK * 3)    // candidate_label (B*K) = 512

// Scratch: full logits (B*S, 6) fp32
__device__ float g_logits[ROWS_TOTAL * NC];

// ---------------------------------------------------------------------------
// Kernel 1: skinny GEMM (32768x1024 @ 1024x6) + bias + argmax predict_label
// Transposed input tile through smem (lane <-> row); W columns read as
// warp-uniform broadcast LDS.128; input read as conflict-free LDS.128.
// HBM-bound by design (134 MB input traffic).
// ---------------------------------------------------------------------------
#define TILE_ROWS 128
#define KC 64
#define PITCH 68   // 272 B lane stride -> conflict-free .128 (272 mod 128 = 16)

__global__ void __launch_bounds__(128)
rpn_gemm_kernel(const float* __restrict__ x, const float* __restrict__ W,
                const float* __restrict__ bias, float* __restrict__ out,
                int out_size)
{
    extern __shared__ float smem[];
    float* s_in = smem;                       // [TILE_ROWS][PITCH]
    float* s_wt = smem + TILE_ROWS * PITCH;   // [6][1024], wt[c][d] = W[d*6+c]

    const int tid  = threadIdx.x;
    const int warp = tid >> 5;
    const int lane = tid & 31;
    const int rowBase = blockIdx.x * TILE_ROWS;

    // Load transposed W into smem (24 KB, once per block)
    for (int i = tid; i < NC * DD; i += 128) {
        int c = i >> 10;          // i / 1024
        int d = i & 1023;
        s_wt[i] = W[d * NC + c];
    }
    __syncthreads();

    float acc0 = 0.f, acc1 = 0.f, acc2 = 0.f, acc3 = 0.f, acc4 = 0.f, acc5 = 0.f;
    const int myrow = warp * 32 + lane;

    for (int kc = 0; kc < DD; kc += KC) {
        // Cooperative coalesced load of [128 rows][64 cols] into smem
        #pragma unroll
        for (int i = 0; i < 16; i++) {
            int linear = i * 128 + tid;
            int r  = linear >> 4;       // 16 float4s per row-chunk
            int c4 = linear & 15;
            float4 v = *(const float4*)&x[(size_t)(rowBase + r) * DD + kc + c4 * 4];
            *(float4*)&s_in[r * PITCH + c4 * 4] = v;
        }
        __syncthreads();

        #pragma unroll
        for (int k4 = 0; k4 < KC / 4; k4++) {
            float4 xv = *(const float4*)&s_in[myrow * PITCH + k4 * 4];
            const float* wbase = &s_wt[kc + k4 * 4];
            float4 w0 = *(const float4*)&wbase[0 * DD];
            float4 w1 = *(const float4*)&wbase[1 * DD];
            float4 w2 = *(const float4*)&wbase[2 * DD];
            float4 w3 = *(const float4*)&wbase[3 * DD];
            float4 w4 = *(const float4*)&wbase[4 * DD];
            float4 w5 = *(const float4*)&wbase[5 * DD];
            acc0 += xv.x * w0.x + xv.y * w0.y + xv.z * w0.z + xv.w * w0.w;
            acc1 += xv.x * w1.x + xv.y * w1.y + xv.z * w1.z + xv.w * w1.w;
            acc2 += xv.x * w2.x + xv.y * w2.y + xv.z * w2.z + xv.w * w2.w;
            acc3 += xv.x * w3.x + xv.y * w3.y + xv.z * w3.z + xv.w * w3.w;
            acc4 += xv.x * w4.x + xv.y * w4.y + xv.z * w4.z + xv.w * w4.w;
            acc5 += xv.x * w5.x + xv.y * w5.y + xv.z * w5.z + xv.w * w5.w;
        }
        __syncthreads();
    }

    const int row = rowBase + myrow;
    float l0 = acc0 + bias[0];
    float l1 = acc1 + bias[1];
    float l2 = acc2 + bias[2];
    float l3 = acc3 + bias[3];
    float l4 = acc4 + bias[4];
    float l5 = acc5 + bias[5];

    float* gl = &g_logits[row * NC];
    gl[0] = l0; gl[1] = l1; gl[2] = l2; gl[3] = l3; gl[4] = l4; gl[5] = l5;

    // predict_label = argmax over C=2 (ties -> 0, matching jnp.argmax)
    int base = OFF_PL + row * AA;
    if (base + 2 < out_size) {
        out[base + 0] = (l1 > l0) ? 1.f : 0.f;
        out[base + 1] = (l3 > l2) ? 1.f : 0.f;
        out[base + 2] = (l5 > l4) ? 1.f : 0.f;
    }
}

// ---------------------------------------------------------------------------
// Kernel 2: per-batch "top-k" = first 64 positive anchors in flat order
// (positives are forced to exactly 2.0 > sigmoid < 1.0, lax.top_k is stable),
// then gather + multi-margin loss + total_idx + candidate_label.
// One warp per batch, single block, deterministic reduction.
// NOTE: labels are int32 (JAX x64 disabled -> astype(int64) is a no-op to i32).
// ---------------------------------------------------------------------------
__global__ void __launch_bounds__(256)
rpn_sample_kernel(const int* __restrict__ labels, float* __restrict__ out,
                  int out_size)
{
    __shared__ int   s_pos[BB * KK];
    __shared__ float s_part[BB];

    const int w    = threadIdx.x >> 5;   // batch id
    const int lane = threadIdx.x & 31;
    const int* lb = labels + (size_t)w * FLAT_PER_B;

    // Defensive init (in case a batch has < 64 positives)
    for (int j = lane; j < KK; j += 32) s_pos[w * KK + j] = 0;
    __syncwarp();

    // Phase A: ordered extraction of first 64 flat indices with label == 1
    int cnt = 0;
    for (int base = 0; base < FLAT_PER_B && cnt < KK; base += 32) {
        int v = lb[base + lane];
        unsigned m = __ballot_sync(0xffffffffu, v == 1);
        int r = cnt + __popc(m & ((1u << lane) - 1u));
        if (v == 1 && r < KK) s_pos[w * KK + r] = base + lane;
        cnt += __popc(m);
    }
    __syncthreads();

    // Phase B: gather logits, compute margin terms + outputs
    float sum = 0.f;
    for (int j = lane; j < KK; j += 32) {
        int p   = s_pos[w * KK + j];
        int seq = p / AA;
        int anc = p - seq * AA;
        int row = w * SS + seq;
        float x0 = g_logits[row * NC + anc * CC + 0];
        float x1 = g_logits[row * NC + anc * CC + 1];
        int y = lb[p];
        float xy = (y == 1) ? x1 : x0;
        float xo = (y == 1) ? x0 : x1;
        // sum_{j != y} max(0, margin - x_y + x_j) / C , C = 2
        sum += fmaxf(0.f, MARGIN - xy + xo) * 0.5f;

        int oi = w * KK + j;
        if (OFF_TI + oi * 3 + 2 < out_size) {
            out[OFF_TI + oi * 3 + 0] = (float)w;
            out[OFF_TI + oi * 3 + 1] = (float)seq;
            out[OFF_TI + oi * 3 + 2] = (float)anc;
        }
        if (OFF_CL + oi < out_size)
            out[OFF_CL + oi] = (x1 > x0) ? 1.f : 0.f;
    }

    // Deterministic reduction: warp shuffle, then thread 0 sums 8 partials
    #pragma unroll
    for (int s = 16; s; s >>= 1) sum += __shfl_down_sync(0xffffffffu, sum, s);
    if (lane == 0) s_part[w] = sum;
    __syncthreads();
    if (threadIdx.x == 0) {
        float tot = 0.f;
        #pragma unroll
        for (int i = 0; i < BB; i++) tot += s_part[i];
        if (out_size > 0) out[OFF_LOSS] = tot / (float)(BB * KK);
    }
}

extern "C" void kernel_launch(void* const* d_in, const int* in_sizes, int n_in,
                              void* d_out, int out_size)
{
    const float* x      = (const float*)d_in[0];    // (B,S,D) f32
    const float* W      = (const float*)d_in[1];    // (D, A*C) f32
    const float* bias   = (const float*)d_in[2];    // (A*C,) f32
    const int*   labels = (const int*)d_in[3];      // (B,S,A) int32 (x64 off!)
    float* out = (float*)d_out;

    const int smem_bytes = (TILE_ROWS * PITCH + NC * DD) * sizeof(float); // 59392
    cudaFuncSetAttribute(rpn_gemm_kernel,
                         cudaFuncAttributeMaxDynamicSharedMemorySize, smem_bytes);

    rpn_gemm_kernel<<<ROWS_TOTAL / TILE_ROWS, 128, smem_bytes>>>(x, W, bias, out, out_size);
    rpn_sample_kernel<<<1, 256>>>(labels, out, out_size);
}

// round 3
// speedup vs baseline: 2.2687x; 2.2687x over previous
#include <cuda_runtime.h>
#include <cuda_bf16.h>
#include <cstdint>

// Problem constants
#define BB 8
#define SS 4096
#define DD 1024
#define AA 3
#define CC 2
#define NC 6            // A*C
#define KK 64           // sample_num
#define MARGIN 5.0f

#define ROWS_TOTAL (BB * SS)      // 32768
#define FLAT_PER_B (SS * AA)      // 12288

// Output packing (float32 concat, verified rel_err=0.0 in R2)
#define OFF_LOSS 0
#define OFF_PL   1                         // predict_label (B,S,A) = 98304
#define OFF_TI   (1 + ROWS_TOTAL * AA)     // total_idx (B*K,3) = 1536
#define OFF_CL   (OFF_TI + BB * KK * 3)    // candidate_label (B*K) = 512

// Scratch: full logits (B*S, 6) fp32
__device__ float g_logits[ROWS_TOTAL * NC];

// ---------------------------------------------------------------------------
// Kernel 1: skinny GEMM (32768x1024 @ 1024x6) + bias + argmax predict_label
// 3-stage cp.async pipeline, KC=32; transposed smem tile (lane<->row),
// broadcast-W LDS; 2 CTAs/SM -> all 256 CTAs resident in one wave.
// ---------------------------------------------------------------------------
#define TILE_ROWS 128
#define KC 32
#define NCHUNK (DD / KC)          // 32
#define STAGES 3
#define PITCH 36                  // 144 B lane stride ≡ 16 mod 128 -> conflict-free .128
#define STAGE_FLOATS (TILE_ROWS * PITCH)   // 4608

__device__ __forceinline__ void cp_async16(void* smem_ptr, const void* gmem_ptr) {
    uint32_t s = (uint32_t)__cvta_generic_to_shared(smem_ptr);
    asm volatile("cp.async.cg.shared.global [%0], [%1], 16;" :: "r"(s), "l"(gmem_ptr));
}

__device__ __forceinline__ void load_chunk(float* s_stage, const float* __restrict__ x,
                                           int rowBase, int kc, int tid) {
    #pragma unroll
    for (int i = 0; i < 8; i++) {
        int linear = i * 128 + tid;
        int r  = linear >> 3;       // 8 float4s per 32-float row
        int c4 = linear & 7;
        cp_async16(&s_stage[r * PITCH + c4 * 4],
                   &x[(size_t)(rowBase + r) * DD + kc + c4 * 4]);
    }
    asm volatile("cp.async.commit_group;");
}

__global__ void __launch_bounds__(128, 2)
rpn_gemm_kernel(const float* __restrict__ x, const float* __restrict__ W,
                const float* __restrict__ bias, float* __restrict__ out)
{
    extern __shared__ float smem[];
    float* s_in = smem;                              // [STAGES][128][PITCH]
    float* s_wt = smem + STAGES * STAGE_FLOATS;      // [6][1024], wt[c][d]

    const int tid  = threadIdx.x;
    const int warp = tid >> 5;
    const int lane = tid & 31;
    const int rowBase = blockIdx.x * TILE_ROWS;
    const int myrow = warp * 32 + lane;

    // Prologue: start chunks 0 and 1 in flight immediately
    load_chunk(s_in + 0 * STAGE_FLOATS, x, rowBase, 0, tid);
    load_chunk(s_in + 1 * STAGE_FLOATS, x, rowBase, KC, tid);

    // Load transposed W into smem (24 KB, once per block; L2-resident after blk 0)
    for (int i = tid; i < NC * DD; i += 128) {
        int c = i >> 10;
        int d = i & 1023;
        s_wt[i] = W[d * NC + c];
    }

    float acc0 = 0.f, acc1 = 0.f, acc2 = 0.f, acc3 = 0.f, acc4 = 0.f, acc5 = 0.f;

    #pragma unroll 1
    for (int c = 0; c < NCHUNK; c++) {
        if (c + 1 < NCHUNK) asm volatile("cp.async.wait_group 1;");
        else                asm volatile("cp.async.wait_group 0;");
        __syncthreads();   // stage c%3 full; all warps done with chunk c-1

        if (c + 2 < NCHUNK)
            load_chunk(s_in + ((c + 2) % STAGES) * STAGE_FLOATS, x, rowBase,
                       (c + 2) * KC, tid);

        const float* sbase = s_in + (c % STAGES) * STAGE_FLOATS + myrow * PITCH;
        const float* wb    = s_wt + c * KC;
        #pragma unroll
        for (int k4 = 0; k4 < KC / 4; k4++) {
            float4 xv = *(const float4*)&sbase[k4 * 4];
            const float* wk = &wb[k4 * 4];
            float4 w0 = *(const float4*)&wk[0 * DD];
            float4 w1 = *(const float4*)&wk[1 * DD];
            float4 w2 = *(const float4*)&wk[2 * DD];
            float4 w3 = *(const float4*)&wk[3 * DD];
            float4 w4 = *(const float4*)&wk[4 * DD];
            float4 w5 = *(const float4*)&wk[5 * DD];
            acc0 += xv.x * w0.x + xv.y * w0.y + xv.z * w0.z + xv.w * w0.w;
            acc1 += xv.x * w1.x + xv.y * w1.y + xv.z * w1.z + xv.w * w1.w;
            acc2 += xv.x * w2.x + xv.y * w2.y + xv.z * w2.z + xv.w * w2.w;
            acc3 += xv.x * w3.x + xv.y * w3.y + xv.z * w3.z + xv.w * w3.w;
            acc4 += xv.x * w4.x + xv.y * w4.y + xv.z * w4.z + xv.w * w4.w;
            acc5 += xv.x * w5.x + xv.y * w5.y + xv.z * w5.z + xv.w * w5.w;
        }
        __syncthreads();
    }

    const int row = rowBase + myrow;
    float l0 = acc0 + bias[0];
    float l1 = acc1 + bias[1];
    float l2 = acc2 + bias[2];
    float l3 = acc3 + bias[3];
    float l4 = acc4 + bias[4];
    float l5 = acc5 + bias[5];

    // g_logits: 3x vectorized STG.64 (row*6*4 is 8-byte aligned)
    float2* gl = (float2*)&g_logits[row * NC];
    gl[0] = make_float2(l0, l1);
    gl[1] = make_float2(l2, l3);
    gl[2] = make_float2(l4, l5);

    // predict_label = argmax over C=2 (ties -> 0, matching jnp.argmax)
    float* pl = &out[OFF_PL + row * AA];
    pl[0] = (l1 > l0) ? 1.f : 0.f;
    pl[1] = (l3 > l2) ? 1.f : 0.f;
    pl[2] = (l5 > l4) ? 1.f : 0.f;
}

// ---------------------------------------------------------------------------
// Kernel 2: per-batch "top-k" = first 64 positive anchors in flat order
// (positives forced to 2.0 > sigmoid < 1.0; lax.top_k stable). One warp per
// batch; labels preloaded 256-wide (MLP=8) so only ~1 DRAM latency exposed.
// ---------------------------------------------------------------------------
__global__ void __launch_bounds__(256)
rpn_sample_kernel(const int* __restrict__ labels, float* __restrict__ out)
{
    __shared__ int   s_pos[BB * KK];
    __shared__ float s_part[BB];

    const int w    = threadIdx.x >> 5;   // batch id
    const int lane = threadIdx.x & 31;
    const int* lb = labels + (size_t)w * FLAT_PER_B;

    for (int j = lane; j < KK; j += 32) s_pos[w * KK + j] = 0;

    // Phase A: preload 256 labels, then ordered ballot extraction
    int v[8];
    #pragma unroll
    for (int i = 0; i < 8; i++) v[i] = lb[i * 32 + lane];

    int cnt = 0;
    #pragma unroll
    for (int i = 0; i < 8; i++) {
        unsigned m = __ballot_sync(0xffffffffu, v[i] == 1);
        int r = cnt + __popc(m & ((1u << lane) - 1u));
        if (v[i] == 1 && r < KK) s_pos[w * KK + r] = i * 32 + lane;
        cnt += __popc(m);
    }
    // Rare fallback: fewer than 64 positives in first 256 slots
    for (int base = 256; base < FLAT_PER_B && cnt < KK; base += 32) {
        int vv = lb[base + lane];
        unsigned m = __ballot_sync(0xffffffffu, vv == 1);
        int r = cnt + __popc(m & ((1u << lane) - 1u));
        if (vv == 1 && r < KK) s_pos[w * KK + r] = base + lane;
        cnt += __popc(m);
    }
    __syncwarp();

    // Phase B: gather logits (float2), margin loss terms + index outputs.
    // Each lane handles j = lane and j = lane+32; issue both gathers up front.
    int p0 = s_pos[w * KK + lane];
    int p1 = s_pos[w * KK + 32 + lane];
    int seq0 = p0 / AA, anc0 = p0 - seq0 * AA;
    int seq1 = p1 / AA, anc1 = p1 - seq1 * AA;
    float2 g0 = *(const float2*)&g_logits[(w * SS + seq0) * NC + anc0 * CC];
    float2 g1 = *(const float2*)&g_logits[(w * SS + seq1) * NC + anc1 * CC];
    int y0 = lb[p0];
    int y1 = lb[p1];

    float sum = 0.f;
    {
        float xy = (y0 == 1) ? g0.y : g0.x;
        float xo = (y0 == 1) ? g0.x : g0.y;
        sum += fmaxf(0.f, MARGIN - xy + xo) * 0.5f;
        int oi = w * KK + lane;
        out[OFF_TI + oi * 3 + 0] = (float)w;
        out[OFF_TI + oi * 3 + 1] = (float)seq0;
        out[OFF_TI + oi * 3 + 2] = (float)anc0;
        out[OFF_CL + oi]         = (g0.y > g0.x) ? 1.f : 0.f;
    }
    {
        float xy = (y1 == 1) ? g1.y : g1.x;
        float xo = (y1 == 1) ? g1.x : g1.y;
        sum += fmaxf(0.f, MARGIN - xy + xo) * 0.5f;
        int oi = w * KK + 32 + lane;
        out[OFF_TI + oi * 3 + 0] = (float)w;
        out[OFF_TI + oi * 3 + 1] = (float)seq1;
        out[OFF_TI + oi * 3 + 2] = (float)anc1;
        out[OFF_CL + oi]         = (g1.y > g1.x) ? 1.f : 0.f;
    }

    #pragma unroll
    for (int s = 16; s; s >>= 1) sum += __shfl_down_sync(0xffffffffu, sum, s);
    if (lane == 0) s_part[w] = sum;
    __syncthreads();
    if (threadIdx.x == 0) {
        float tot = 0.f;
        #pragma unroll
        for (int i = 0; i < BB; i++) tot += s_part[i];
        out[OFF_LOSS] = tot / (float)(BB * KK);
    }
}

extern "C" void kernel_launch(void* const* d_in, const int* in_sizes, int n_in,
                              void* d_out, int out_size)
{
    const float* x      = (const float*)d_in[0];    // (B,S,D) f32
    const float* W      = (const float*)d_in[1];    // (D, A*C) f32
    const float* bias   = (const float*)d_in[2];    // (A*C,) f32
    const int*   labels = (const int*)d_in[3];      // (B,S,A) int32
    float* out = (float*)d_out;

    const int smem_bytes = (STAGES * STAGE_FLOATS + NC * DD) * sizeof(float); // 79872
    cudaFuncSetAttribute(rpn_gemm_kernel,
                         cudaFuncAttributeMaxDynamicSharedMemorySize, smem_bytes);

    rpn_gemm_kernel<<<ROWS_TOTAL / TILE_ROWS, 128, smem_bytes>>>(x, W, bias, out);
    rpn_sample_kernel<<<1, 256>>>(labels, out);
}